// round 10
// baseline (speedup 1.0000x reference)
#include <cuda_runtime.h>
#include <cuda_fp16.h>
#include <cstdint>

// ===========================================================================
// 3 kernels:
//  kB: w2 -> g_Bh[c][kk] fp16 (kk = k*128+j)
//  kX: x[m] -> g_Xh[m][u][j] fp16, u = l*16+h+2 (ldsm-ready, zero pads baked)
//  kMain: grid (cq=4, m=1024), 448 thr, 2 CTAs/SM.
//    smem: xs 61,472B (226x136 halves; overlaid by t4s 224x74 after GEMM)
//          Bs 50,176B (64 c x 392 halves)
//    GEMM: warp w = l-tile (14 warps), m16 x n64, K=384 (24 k16 steps),
//          mma.sync m16n8k16 f16->f32; A/B via ldmatrix.x4.
//    Epilogue: out[m, cq*64+cl, p, b] = w1[C,0]*t4[l1,b,C] + w1[C,1]*t4[l2,b,C]
// ===========================================================================

__device__ __half g_Bh[256 * 384];                  // [c][kk]
__device__ __half g_Xh[(size_t)1024 * 226 * 128];   // [m][u][j]

__device__ __forceinline__ uint32_t smem_u32(const void* p) {
    uint32_t a;
    asm("{ .reg .u64 t; cvta.to.shared.u64 t, %1; cvt.u32.u64 %0, t; }" : "=r"(a) : "l"(p));
    return a;
}

__global__ __launch_bounds__(256) void kB(const float* __restrict__ w2) {
    int i = blockIdx.x * 256 + threadIdx.x;          // 98304 total
    if (i >= 98304) return;
    int c  = i / 384;
    int kk = i - c * 384;
    int k  = kk >> 7;
    int j  = kk & 127;
    g_Bh[i] = __float2half(w2[j * 768 + k * 256 + c]);
}

// x (f32, [j][l*14+h]) -> g_Xh[m][u][j] with u = l*16+h+2; pad rows zeroed.
__global__ __launch_bounds__(256) void kX(const float* __restrict__ x) {
    extern __shared__ float scr[];                   // [j][197] (conflict-free cols)
    const int m = blockIdx.x;
    const float* xm = x + (size_t)m * 25088;
    for (int i = threadIdx.x; i < 25088; i += 256) { // coalesced both sides
        int j  = i / 196;
        int lh = i - j * 196;
        scr[j * 197 + lh] = xm[i];
    }
    __syncthreads();
    __half* dst = g_Xh + (size_t)m * 226 * 128;
    for (int i = threadIdx.x; i < 226 * 128; i += 256) {
        int u = i >> 7;
        int j = i & 127;
        int q = u & 15;
        float v = 0.f;
        if (q >= 2 && u < 224) {                     // valid data row
            int l = u >> 4;
            int h = q - 2;
            v = scr[j * 197 + l * 14 + h];           // stride 197: conflict-free
        }
        dst[i] = __float2half(v);                    // coalesced 2B stores
    }
}

static constexpr int XS_STRIDE = 136;   // halves (272B rows; ldsm conflict-free)
static constexpr int BS_STRIDE = 392;   // halves (784B rows; ldsm conflict-free)
static constexpr int T4_STRIDE = 74;    // halves (37-word rows: 5b mod 32, c-free)

static constexpr int XS_OFF = 0;                      // 226*136*2 = 61472 B
static constexpr int BS_OFF = 61472;                  // 64*392*2  = 50176 B
static constexpr int SMEM_BYTES = 111648;
static constexpr int NT = 448;                        // 14 warps

__global__ __launch_bounds__(NT, 2) void kMain(const float* __restrict__ w1,
                                               float* __restrict__ out) {
    extern __shared__ char smem[];
    __half* xs  = (__half*)(smem + XS_OFF);
    __half* Bs  = (__half*)(smem + BS_OFF);
    __half* t4s = (__half*)(smem + XS_OFF);   // OVERLAYS xs (xs dead post-GEMM)

    const int tid  = threadIdx.x;
    const int cq   = blockIdx.x;              // 0..3  (channel quarter)
    const int m    = blockIdx.y;
    const int wid  = tid >> 5;
    const int lane = tid & 31;

    // ---- build: pure coalesced copies from pre-transposed gmem ----
    {
        const uint32_t* src = (const uint32_t*)(g_Xh + (size_t)m * 226 * 128);
        uint32_t* dst = (uint32_t*)xs;
        for (int i = tid; i < 226 * 64; i += NT) {     // 14464 words
            int u = i >> 6, w = i & 63;
            dst[u * 68 + w] = src[i];                  // banks 4u+w: conflict-free
        }
    }
    {
        const uint32_t* src = (const uint32_t*)g_Bh + cq * 64 * 192;
        uint32_t* dst = (uint32_t*)Bs;
        for (int i = tid; i < 64 * 192; i += NT) {     // 12288 words
            int c = i / 192, w = i - c * 192;
            dst[c * 196 + w] = src[i];                 // banks 4c+w: conflict-free
        }
    }

    // ---- per-warp GEMM constants: warp = l-tile, n64 = all 64 channels ----
    const uint32_t a_pre = smem_u32(xs) +
        (uint32_t)(((wid * 16 + (lane & 15)) * XS_STRIDE + ((lane >> 4) << 3)) * 2);
    const int n_in16 = (((lane >> 4) & 1) << 3) + (lane & 7);
    const int k_half = ((lane >> 3) & 1) << 3;
    const uint32_t b_pre = smem_u32(Bs) +
        (uint32_t)((n_in16 * BS_STRIDE + k_half) * 2);

    float d[8][4];
    #pragma unroll
    for (int i = 0; i < 8; i++)
        #pragma unroll
        for (int q = 0; q < 4; q++) d[i][q] = 0.f;

    __syncthreads();

    // ---- GEMM: 24 k16 steps ----
    #pragma unroll 4
    for (int s = 0; s < 24; s++) {
        const int tap = s >> 3;
        uint32_t a_addr = a_pre + (uint32_t)(tap * (XS_STRIDE * 2) + (s & 7) * 32);
        uint32_t a0, a1, a2, a3;
        asm volatile("ldmatrix.sync.aligned.m8n8.x4.shared.b16 {%0,%1,%2,%3}, [%4];"
                     : "=r"(a0), "=r"(a1), "=r"(a2), "=r"(a3) : "r"(a_addr));
        uint32_t b_addr = b_pre + (uint32_t)(s * 32);
        #pragma unroll
        for (int q = 0; q < 4; q++) {
            uint32_t b0, b1, b2, b3;
            asm volatile("ldmatrix.sync.aligned.m8n8.x4.shared.b16 {%0,%1,%2,%3}, [%4];"
                         : "=r"(b0), "=r"(b1), "=r"(b2), "=r"(b3) : "r"(b_addr));
            b_addr += 16u * BS_STRIDE * 2u;
            asm volatile("mma.sync.aligned.m16n8k16.row.col.f32.f16.f16.f32 "
                         "{%0,%1,%2,%3}, {%4,%5,%6,%7}, {%8,%9}, {%0,%1,%2,%3};"
                         : "+f"(d[2*q][0]), "+f"(d[2*q][1]),
                           "+f"(d[2*q][2]), "+f"(d[2*q][3])
                         : "r"(a0), "r"(a1), "r"(a2), "r"(a3), "r"(b0), "r"(b1));
            asm volatile("mma.sync.aligned.m16n8k16.row.col.f32.f16.f16.f32 "
                         "{%0,%1,%2,%3}, {%4,%5,%6,%7}, {%8,%9}, {%0,%1,%2,%3};"
                         : "+f"(d[2*q+1][0]), "+f"(d[2*q+1][1]),
                           "+f"(d[2*q+1][2]), "+f"(d[2*q+1][3])
                         : "r"(a0), "r"(a1), "r"(a2), "r"(a3), "r"(b2), "r"(b3));
        }
    }
    __syncthreads();   // all warps done reading xs -> safe to overlay t4s

    // ---- t4s store (fp16, stride 74): rows wid*16+q, q=0..15 all written ----
    {
        const int q0 = lane >> 2;
        const int tq = lane & 3;
        const int rbase = wid * 16;
        #pragma unroll
        for (int i = 0; i < 8; i++) {
            const int c0 = i * 8 + tq * 2;
            *(__half2*)(t4s + (rbase + q0) * T4_STRIDE + c0) =
                __floats2half2_rn(d[i][0], d[i][1]);
            *(__half2*)(t4s + (rbase + q0 + 8) * T4_STRIDE + c0) =
                __floats2half2_rn(d[i][2], d[i][3]);
        }
    }
    __syncthreads();

    // ---- epilogue: two-tap combine, fully coalesced out stores ----
    float* om = out + (size_t)m * 50176 + cq * 12544;
    const float2* w1v = (const float2*)w1;
    for (int i = tid; i < 12544; i += NT) {
        int cl = i / 196;                 // 0..63
        int rr = i - cl * 196;
        int p  = rr / 14;
        int b  = rr - p * 14;
        int l1 = (p == 0) ? 13 : p - 1;
        int l2 = (p < 2) ? p + 12 : p - 2;
        float2 wv = w1v[cq * 64 + cl];
        float v = wv.x * __half2float(t4s[(l1 * 16 + 1 + b) * T4_STRIDE + cl])
                + wv.y * __half2float(t4s[(l2 * 16 + 1 + b) * T4_STRIDE + cl]);
        om[i] = v;
    }
}

// ===========================================================================
extern "C" void kernel_launch(void* const* d_in, const int* in_sizes, int n_in,
                              void* d_out, int out_size) {
    const float* x  = (const float*)d_in[0];   // (1024, 1792, 14)
    const float* w1 = (const float*)d_in[1];   // (256, 2)
    const float* w2 = (const float*)d_in[2];   // (128, 3, 256)
    float* out = (float*)d_out;                // (1024, 256, 14, 14)

    static int attr_done = 0;
    if (!attr_done) {
        cudaFuncSetAttribute(kX, cudaFuncAttributeMaxDynamicSharedMemorySize, 100864);
        cudaFuncSetAttribute(kMain, cudaFuncAttributeMaxDynamicSharedMemorySize,
                             SMEM_BYTES);
        attr_done = 1;
    }

    kB<<<384, 256>>>(w2);
    kX<<<1024, 256, 100864>>>(x);
    dim3 gm(4, 1024);
    kMain<<<gm, NT, SMEM_BYTES>>>(w1, out);
}

// round 11
// speedup vs baseline: 1.3507x; 1.3507x over previous
#include <cuda_runtime.h>
#include <cuda_fp16.h>
#include <cstdint>

// ===========================================================================
// One CTA per m, 1024 threads = 32 warps (28 active in GEMM), warp m16 x n64.
// GEMM rows grouped by l: l-tile covers rows q=0..15 (q=1..14 <-> n=q-1).
// xs[u][j]: u = l*16 + h + 2; rows u%16 in {0,1} AND rows 224/225 are zero
// pads (row 224 feeds valid (l=13,n=13,tap=2) - must be zeroed every launch).
// t4s stride = 138 halves (69 words, odd) -> epilogue LDS conflict-free.
// Phasing (6 barriers): build+Bs0 | gemm0 | t4s0+Bs1 | epi0;gemm1 | t4s1 | epi1
// ===========================================================================

__device__ __half g_Bh[256 * 384];   // w2^T fp16: [c][kk], kk = k*128+j

__device__ __forceinline__ uint32_t smem_u32(const void* p) {
    uint32_t a;
    asm("{ .reg .u64 t; cvta.to.shared.u64 t, %1; cvt.u32.u64 %0, t; }" : "=r"(a) : "l"(p));
    return a;
}

__global__ __launch_bounds__(256) void kB(const float* __restrict__ w2) {
    int i = blockIdx.x * 256 + threadIdx.x;          // 98304 total
    if (i >= 98304) return;
    int c  = i / 384;
    int kk = i - c * 384;
    int k  = kk >> 7;
    int j  = kk & 127;
    g_Bh[i] = __float2half(w2[j * 768 + k * 256 + c]);
}

static constexpr int XS_STRIDE = 136;   // halves (272B rows; ldsm conflict-free)
static constexpr int BS_STRIDE = 392;   // halves (784B rows; ldsm conflict-free)
static constexpr int T4_STRIDE = 138;   // halves (69 words, odd -> conflict-free)

static constexpr int XS_OFF = 0;                      // 226*136*2 = 61472 B
static constexpr int BS_OFF = 61472;                  // 128*392*2 = 100352 B
static constexpr int T4_OFF = 161824;                 // 224*138*2 = 61824 B
static constexpr int SMEM_BYTES = 223648;

static constexpr int NT = 1024;         // 32 warps; 28 active in GEMM

struct GemmCtx { uint32_t a_pre, b_pre; bool active; };

__device__ __forceinline__ void gemm_phase(float (&d)[8][4], const GemmCtx& g) {
    #pragma unroll
    for (int i = 0; i < 8; i++)
        #pragma unroll
        for (int q = 0; q < 4; q++) d[i][q] = 0.f;
    if (!g.active) return;
    #pragma unroll 4
    for (int s = 0; s < 24; s++) {
        const int tap = s >> 3;
        uint32_t a_addr = g.a_pre + (uint32_t)(tap * (XS_STRIDE * 2) + (s & 7) * 32);
        uint32_t a0, a1, a2, a3;
        asm volatile("ldmatrix.sync.aligned.m8n8.x4.shared.b16 {%0,%1,%2,%3}, [%4];"
                     : "=r"(a0), "=r"(a1), "=r"(a2), "=r"(a3) : "r"(a_addr));
        uint32_t b_addr = g.b_pre + (uint32_t)(s * 32);
        #pragma unroll
        for (int q = 0; q < 4; q++) {
            uint32_t b0, b1, b2, b3;
            asm volatile("ldmatrix.sync.aligned.m8n8.x4.shared.b16 {%0,%1,%2,%3}, [%4];"
                         : "=r"(b0), "=r"(b1), "=r"(b2), "=r"(b3) : "r"(b_addr));
            b_addr += 16u * BS_STRIDE * 2u;
            asm volatile("mma.sync.aligned.m16n8k16.row.col.f32.f16.f16.f32 "
                         "{%0,%1,%2,%3}, {%4,%5,%6,%7}, {%8,%9}, {%0,%1,%2,%3};"
                         : "+f"(d[2*q][0]), "+f"(d[2*q][1]),
                           "+f"(d[2*q][2]), "+f"(d[2*q][3])
                         : "r"(a0), "r"(a1), "r"(a2), "r"(a3), "r"(b0), "r"(b1));
            asm volatile("mma.sync.aligned.m16n8k16.row.col.f32.f16.f16.f32 "
                         "{%0,%1,%2,%3}, {%4,%5,%6,%7}, {%8,%9}, {%0,%1,%2,%3};"
                         : "+f"(d[2*q+1][0]), "+f"(d[2*q+1][1]),
                           "+f"(d[2*q+1][2]), "+f"(d[2*q+1][3])
                         : "r"(a0), "r"(a1), "r"(a2), "r"(a3), "r"(b2), "r"(b3));
        }
    }
}

__device__ __forceinline__ void t4_store(float (&d)[8][4], __half* t4s,
                                         int mt, int cbase, int lane) {
    const int q0 = lane >> 2;
    const int tq = lane & 3;
    const int rbase = mt * 16;
    #pragma unroll
    for (int i = 0; i < 8; i++) {
        const int c0 = (cbase + i) * 8 + tq * 2;
        *(__half2*)(t4s + (rbase + q0) * T4_STRIDE + c0) =
            __floats2half2_rn(d[i][0], d[i][1]);
        *(__half2*)(t4s + (rbase + q0 + 8) * T4_STRIDE + c0) =
            __floats2half2_rn(d[i][2], d[i][3]);
    }
}

__global__ __launch_bounds__(NT, 1) void kMain(const float* __restrict__ x,
                                               const float* __restrict__ w1,
                                               float* __restrict__ out) {
    extern __shared__ char smem[];
    __half* xs  = (__half*)(smem + XS_OFF);
    __half* Bs  = (__half*)(smem + BS_OFF);
    __half* t4s = (__half*)(smem + T4_OFF);

    const int tid  = threadIdx.x;
    const int m    = blockIdx.x;
    const int wid  = tid >> 5;
    const int lane = tid & 31;

    // ================= Phase A: zero pads + build xs + load Bs(0) ==========
    {   // rows u%16 in {0,1} (28 rows) plus rows 224,225 (r=28,29)
        uint32_t* xz = (uint32_t*)xs;
        for (int i = tid; i < 30 * 64; i += NT) {
            int r   = i >> 6;
            int row = (r >> 1) * 16 + (r & 1);
            xz[(row * XS_STRIDE) / 2 + (i & 63)] = 0;
        }
    }
    const float* xm = x + (size_t)m * 25088;
    for (int i = tid; i < 25088; i += NT) {
        int j  = i / 196;
        int lh = i - j * 196;
        int l  = lh / 14;
        int h  = lh - l * 14;
        xs[(l * 16 + h + 2) * XS_STRIDE + j] = __float2half(xm[i]);
    }
    {
        const uint32_t* src = (const uint32_t*)g_Bh;          // hc=0
        for (int i = tid; i < 128 * 192; i += NT) {
            int c  = i / 192;
            int kw = i - c * 192;
            *(uint32_t*)(Bs + c * BS_STRIDE + kw * 2) = src[i];
        }
    }

    // ---- per-warp constants: 28 active warps = 14 m-tiles x 2 ngrps ----
    const bool active = wid < 28;
    const int  mt     = active ? (wid % 14) : 0;
    const int  ngrp   = active ? (wid / 14) : 0;
    const int  cbase  = ngrp * 8;

    GemmCtx g;
    g.active = active;
    g.a_pre  = smem_u32(xs) +
        (uint32_t)(((mt * 16 + (lane & 15)) * XS_STRIDE + ((lane >> 4) << 3)) * 2);
    {
        const int n_in16 = (((lane >> 4) & 1) << 3) + (lane & 7);
        const int k_half = ((lane >> 3) & 1) << 3;
        g.b_pre = smem_u32(Bs) +
            (uint32_t)(((cbase * 8 + n_in16) * BS_STRIDE + k_half) * 2);
    }

    float* om = out + (size_t)m * 50176;
    const float2* w1v = (const float2*)w1;

    float d[8][4];
    __syncthreads();

    // ================= hc = 0 ==============================================
    gemm_phase(d, g);
    __syncthreads();

    // t4s store(0) + Bs(1) load
    if (active) t4_store(d, t4s, mt, cbase, lane);
    {
        const uint32_t* src = (const uint32_t*)(g_Bh + 128 * 384);   // hc=1
        for (int i = tid; i < 128 * 192; i += NT) {
            int c  = i / 192;
            int kw = i - c * 192;
            *(uint32_t*)(Bs + c * BS_STRIDE + kw * 2) = src[i];
        }
    }
    __syncthreads();

    // epilogue(0) then gemm(1); disjoint read sets (t4s vs xs/Bs), no barrier
    for (int i = tid; i < 25088; i += NT) {
        int cl = i / 196;
        int rr = i - cl * 196;
        int p  = rr / 14;
        int b  = rr - p * 14;
        int l1 = (p == 0) ? 13 : p - 1;
        int l2 = (p < 2) ? p + 12 : p - 2;
        float2 wv = w1v[cl];                              // hc=0
        float v = wv.x * __half2float(t4s[(l1 * 16 + 1 + b) * T4_STRIDE + cl])
                + wv.y * __half2float(t4s[(l2 * 16 + 1 + b) * T4_STRIDE + cl]);
        om[i] = v;
    }
    gemm_phase(d, g);
    __syncthreads();

    // t4s store(1)
    if (active) t4_store(d, t4s, mt, cbase, lane);
    __syncthreads();

    // epilogue(1)
    for (int i = tid; i < 25088; i += NT) {
        int cl = i / 196;
        int rr = i - cl * 196;
        int p  = rr / 14;
        int b  = rr - p * 14;
        int l1 = (p == 0) ? 13 : p - 1;
        int l2 = (p < 2) ? p + 12 : p - 2;
        float2 wv = w1v[128 + cl];                        // hc=1
        float v = wv.x * __half2float(t4s[(l1 * 16 + 1 + b) * T4_STRIDE + cl])
                + wv.y * __half2float(t4s[(l2 * 16 + 1 + b) * T4_STRIDE + cl]);
        om[25088 + i] = v;
    }
}

// ===========================================================================
extern "C" void kernel_launch(void* const* d_in, const int* in_sizes, int n_in,
                              void* d_out, int out_size) {
    const float* x  = (const float*)d_in[0];   // (1024, 1792, 14)
    const float* w1 = (const float*)d_in[1];   // (256, 2)
    const float* w2 = (const float*)d_in[2];   // (128, 3, 256)
    float* out = (float*)d_out;                // (1024, 256, 14, 14)

    static int attr_done = 0;
    if (!attr_done) {
        cudaFuncSetAttribute(kMain, cudaFuncAttributeMaxDynamicSharedMemorySize,
                             SMEM_BYTES);
        attr_done = 1;
    }

    kB<<<384, 256>>>(w2);
    kMain<<<1024, NT, SMEM_BYTES>>>(x, w1, out);
}

// round 12
// speedup vs baseline: 1.3867x; 1.0267x over previous
#include <cuda_runtime.h>
#include <cuda_fp16.h>
#include <cstdint>

// ===========================================================================
// One CTA per m, 1024 threads = 32 warps (28 active in GEMM), warp m16 x n64.
// GEMM rows grouped by l: l-tile covers rows q=0..15 (q=1..14 <-> n=q-1).
// xs[u][j]: u = l*16 + h + 2; rows u%16 in {0,1} AND rows 224/225 are zero
// pads (row 224 feeds valid (l=13,n=13,tap=2) - zeroed every launch).
// t4s stride = 138 halves (69 words, odd) -> epilogue LDS conflict-free.
// Phasing (6 barriers): build+Bs0 | gemm0 | t4s0+Bs1 | epi0;gemm1 | t4s1 | epi1
// R12: all build/epilogue index math is incremental (no div/mod in loops).
// ===========================================================================

__device__ __half g_Bh[256 * 384];   // w2^T fp16: [c][kk], kk = k*128+j

__device__ __forceinline__ uint32_t smem_u32(const void* p) {
    uint32_t a;
    asm("{ .reg .u64 t; cvta.to.shared.u64 t, %1; cvt.u32.u64 %0, t; }" : "=r"(a) : "l"(p));
    return a;
}

__global__ __launch_bounds__(256) void kB(const float* __restrict__ w2) {
    int i = blockIdx.x * 256 + threadIdx.x;          // 98304 total
    if (i >= 98304) return;
    int c  = i / 384;
    int kk = i - c * 384;
    int k  = kk >> 7;
    int j  = kk & 127;
    g_Bh[i] = __float2half(w2[j * 768 + k * 256 + c]);
}

static constexpr int XS_STRIDE = 136;   // halves (272B rows; ldsm conflict-free)
static constexpr int BS_STRIDE = 392;   // halves (784B rows; ldsm conflict-free)
static constexpr int T4_STRIDE = 138;   // halves (69 words, odd -> conflict-free)

static constexpr int XS_OFF = 0;                      // 226*136*2 = 61472 B
static constexpr int BS_OFF = 61472;                  // 128*392*2 = 100352 B
static constexpr int T4_OFF = 161824;                 // 224*138*2 = 61824 B
static constexpr int SMEM_BYTES = 223648;

static constexpr int NT = 1024;         // 32 warps; 28 active in GEMM

struct GemmCtx { uint32_t a_pre, b_pre; bool active; };

__device__ __forceinline__ void gemm_phase(float (&d)[8][4], const GemmCtx& g) {
    #pragma unroll
    for (int i = 0; i < 8; i++)
        #pragma unroll
        for (int q = 0; q < 4; q++) d[i][q] = 0.f;
    if (!g.active) return;
    #pragma unroll 4
    for (int s = 0; s < 24; s++) {
        const int tap = s >> 3;
        uint32_t a_addr = g.a_pre + (uint32_t)(tap * (XS_STRIDE * 2) + (s & 7) * 32);
        uint32_t a0, a1, a2, a3;
        asm volatile("ldmatrix.sync.aligned.m8n8.x4.shared.b16 {%0,%1,%2,%3}, [%4];"
                     : "=r"(a0), "=r"(a1), "=r"(a2), "=r"(a3) : "r"(a_addr));
        uint32_t b_addr = g.b_pre + (uint32_t)(s * 32);
        #pragma unroll
        for (int q = 0; q < 4; q++) {
            uint32_t b0, b1, b2, b3;
            asm volatile("ldmatrix.sync.aligned.m8n8.x4.shared.b16 {%0,%1,%2,%3}, [%4];"
                         : "=r"(b0), "=r"(b1), "=r"(b2), "=r"(b3) : "r"(b_addr));
            b_addr += 16u * BS_STRIDE * 2u;
            asm volatile("mma.sync.aligned.m16n8k16.row.col.f32.f16.f16.f32 "
                         "{%0,%1,%2,%3}, {%4,%5,%6,%7}, {%8,%9}, {%0,%1,%2,%3};"
                         : "+f"(d[2*q][0]), "+f"(d[2*q][1]),
                           "+f"(d[2*q][2]), "+f"(d[2*q][3])
                         : "r"(a0), "r"(a1), "r"(a2), "r"(a3), "r"(b0), "r"(b1));
            asm volatile("mma.sync.aligned.m16n8k16.row.col.f32.f16.f16.f32 "
                         "{%0,%1,%2,%3}, {%4,%5,%6,%7}, {%8,%9}, {%0,%1,%2,%3};"
                         : "+f"(d[2*q+1][0]), "+f"(d[2*q+1][1]),
                           "+f"(d[2*q+1][2]), "+f"(d[2*q+1][3])
                         : "r"(a0), "r"(a1), "r"(a2), "r"(a3), "r"(b2), "r"(b3));
        }
    }
}

__device__ __forceinline__ void t4_store(float (&d)[8][4], __half* t4s,
                                         int mt, int cbase, int lane) {
    const int q0 = lane >> 2;
    const int tq = lane & 3;
    const int rbase = mt * 16;
    #pragma unroll
    for (int i = 0; i < 8; i++) {
        const int c0 = (cbase + i) * 8 + tq * 2;
        *(__half2*)(t4s + (rbase + q0) * T4_STRIDE + c0) =
            __floats2half2_rn(d[i][0], d[i][1]);
        *(__half2*)(t4s + (rbase + q0 + 8) * T4_STRIDE + c0) =
            __floats2half2_rn(d[i][2], d[i][3]);
    }
}

// Incremental-index epilogue: walks i = tid + 1024*it over 25088 elements,
// maintaining (cl, rr, p, b) with adds/wraps only. 1024 = 5*196+44, 44 = 3*14+2.
__device__ __forceinline__ void epilogue(const __half* t4s, const float2* w1v,
                                         float* om, int tid, int w1off) {
    int cl = tid / 196;                 // one division per thread, outside loop
    int rr = tid - cl * 196;
    int p  = rr / 14;
    int b  = rr - p * 14;
    for (int i = tid; i < 25088; i += 1024) {
        int l1 = (p == 0) ? 13 : p - 1;
        int l2 = (p < 2) ? p + 12 : p - 2;
        float2 wv = w1v[w1off + cl];
        float v = wv.x * __half2float(t4s[(l1 * 16 + 1 + b) * T4_STRIDE + cl])
                + wv.y * __half2float(t4s[(l2 * 16 + 1 + b) * T4_STRIDE + cl]);
        om[i] = v;
        // advance by 1024: cl += 5, rr += 44 (p += 3, b += 2), with wraps
        cl += 5; p += 3; b += 2;
        if (b >= 14) { b -= 14; p += 1; }
        if (p >= 14) { p -= 14; cl += 1; }   // rr wrapped past 196
    }
}

__global__ __launch_bounds__(NT, 1) void kMain(const float* __restrict__ x,
                                               const float* __restrict__ w1,
                                               float* __restrict__ out) {
    extern __shared__ char smem[];
    __half* xs  = (__half*)(smem + XS_OFF);
    __half* Bs  = (__half*)(smem + BS_OFF);
    __half* t4s = (__half*)(smem + T4_OFF);

    const int tid  = threadIdx.x;
    const int m    = blockIdx.x;
    const int wid  = tid >> 5;
    const int lane = tid & 31;

    // ================= Phase A: zero pads + build xs + load Bs(0) ==========
    {   // rows u%16 in {0,1} (28 rows) plus rows 224,225 (r=28,29)
        uint32_t* xz = (uint32_t*)xs;
        for (int i = tid; i < 30 * 64; i += NT) {
            int r   = i >> 6;
            int row = (r >> 1) * 16 + (r & 1);
            xz[(row * XS_STRIDE) / 2 + (i & 63)] = 0;
        }
    }
    {   // build xs with incremental (j, l, h) tracking
        const float* xm = x + (size_t)m * 25088;
        int j = tid / 196;
        int lh = tid - j * 196;
        int l  = lh / 14;
        int h  = lh - l * 14;
        for (int i = tid; i < 25088; i += 1024) {
            xs[(l * 16 + h + 2) * XS_STRIDE + j] = __float2half(xm[i]);
            j += 5; l += 3; h += 2;                     // lh += 44
            if (h >= 14) { h -= 14; l += 1; }
            if (l >= 14) { l -= 14; j += 1; }           // lh wrapped past 196
        }
    }
    {
        const uint32_t* src = (const uint32_t*)g_Bh;          // hc=0
        for (int i = tid; i < 128 * 192; i += NT) {
            int c  = i / 192;
            int kw = i - c * 192;
            *(uint32_t*)(Bs + c * BS_STRIDE + kw * 2) = src[i];
        }
    }

    // ---- per-warp constants: 28 active warps = 14 m-tiles x 2 ngrps ----
    const bool active = wid < 28;
    const int  mt     = active ? (wid % 14) : 0;
    const int  ngrp   = active ? (wid / 14) : 0;
    const int  cbase  = ngrp * 8;

    GemmCtx g;
    g.active = active;
    g.a_pre  = smem_u32(xs) +
        (uint32_t)(((mt * 16 + (lane & 15)) * XS_STRIDE + ((lane >> 4) << 3)) * 2);
    {
        const int n_in16 = (((lane >> 4) & 1) << 3) + (lane & 7);
        const int k_half = ((lane >> 3) & 1) << 3;
        g.b_pre = smem_u32(Bs) +
            (uint32_t)(((cbase * 8 + n_in16) * BS_STRIDE + k_half) * 2);
    }

    float* om = out + (size_t)m * 50176;
    const float2* w1v = (const float2*)w1;

    float d[8][4];
    __syncthreads();

    // ================= hc = 0 ==============================================
    gemm_phase(d, g);
    __syncthreads();

    // t4s store(0) + Bs(1) load
    if (active) t4_store(d, t4s, mt, cbase, lane);
    {
        const uint32_t* src = (const uint32_t*)(g_Bh + 128 * 384);   // hc=1
        for (int i = tid; i < 128 * 192; i += NT) {
            int c  = i / 192;
            int kw = i - c * 192;
            *(uint32_t*)(Bs + c * BS_STRIDE + kw * 2) = src[i];
        }
    }
    __syncthreads();

    // epilogue(0) then gemm(1); disjoint read sets (t4s vs xs/Bs), no barrier
    epilogue(t4s, w1v, om, tid, 0);
    gemm_phase(d, g);
    __syncthreads();

    // t4s store(1)
    if (active) t4_store(d, t4s, mt, cbase, lane);
    __syncthreads();

    // epilogue(1)
    epilogue(t4s, w1v, om + 25088, tid, 128);
}

// ===========================================================================
extern "C" void kernel_launch(void* const* d_in, const int* in_sizes, int n_in,
                              void* d_out, int out_size) {
    const float* x  = (const float*)d_in[0];   // (1024, 1792, 14)
    const float* w1 = (const float*)d_in[1];   // (256, 2)
    const float* w2 = (const float*)d_in[2];   // (128, 3, 256)
    float* out = (float*)d_out;                // (1024, 256, 14, 14)

    static int attr_done = 0;
    if (!attr_done) {
        cudaFuncSetAttribute(kMain, cudaFuncAttributeMaxDynamicSharedMemorySize,
                             SMEM_BYTES);
        attr_done = 1;
    }

    kB<<<384, 256>>>(w2);
    kMain<<<1024, NT, SMEM_BYTES>>>(x, w1, out);
}

// round 13
// speedup vs baseline: 1.4515x; 1.0467x over previous
#include <cuda_runtime.h>
#include <cuda_fp16.h>
#include <cstdint>

// ===========================================================================
// One CTA per m, 1024 threads = 32 warps (28 active in GEMM), warp m32 x n32.
// Warp w: mpair = w%7 -> m-tiles (2*mpair, 2*mpair+1); ngrp = w/7 (0..3) ->
// n8-tiles [ngrp*4, ngrp*4+4) = 32 channels. 2.0 smem-wavefronts per MMA.
// GEMM rows grouped by l: l-tile covers rows q=0..15 (q=1..14 <-> n=q-1).
// xs[u][j]: u = l*16 + h + 2; rows u%16 in {0,1} AND rows 224/225 are zero
// pads (row 224 feeds valid (l=13,n=13,tap=2) - zeroed every launch).
// t4s stride = 138 halves (69 words, odd) -> epilogue LDS conflict-free.
// Phasing (6 barriers): build+Bs0 | gemm0 | t4s0+Bs1 | epi0;gemm1 | t4s1 | epi1
// ===========================================================================

__device__ __half g_Bh[256 * 384];   // w2^T fp16: [c][kk], kk = k*128+j

__device__ __forceinline__ uint32_t smem_u32(const void* p) {
    uint32_t a;
    asm("{ .reg .u64 t; cvta.to.shared.u64 t, %1; cvt.u32.u64 %0, t; }" : "=r"(a) : "l"(p));
    return a;
}

__global__ __launch_bounds__(256) void kB(const float* __restrict__ w2) {
    int i = blockIdx.x * 256 + threadIdx.x;          // 98304 total
    if (i >= 98304) return;
    int c  = i / 384;
    int kk = i - c * 384;
    int k  = kk >> 7;
    int j  = kk & 127;
    g_Bh[i] = __float2half(w2[j * 768 + k * 256 + c]);
}

static constexpr int XS_STRIDE = 136;   // halves (272B rows; ldsm conflict-free)
static constexpr int BS_STRIDE = 392;   // halves (784B rows; ldsm conflict-free)
static constexpr int T4_STRIDE = 138;   // halves (69 words, odd -> conflict-free)

static constexpr int XS_OFF = 0;                      // 226*136*2 = 61472 B
static constexpr int BS_OFF = 61472;                  // 128*392*2 = 100352 B
static constexpr int T4_OFF = 161824;                 // 224*138*2 = 61824 B
static constexpr int SMEM_BYTES = 223648;

static constexpr int NT = 1024;         // 32 warps; 28 active in GEMM

struct GemmCtx { uint32_t a_pre0, a_pre1, b_pre; bool active; };

__device__ __forceinline__ void gemm_phase(float (&d)[2][4][4], const GemmCtx& g) {
    #pragma unroll
    for (int mi = 0; mi < 2; mi++)
        #pragma unroll
        for (int i = 0; i < 4; i++)
            #pragma unroll
            for (int q = 0; q < 4; q++) d[mi][i][q] = 0.f;
    if (!g.active) return;
    #pragma unroll 4
    for (int s = 0; s < 24; s++) {
        const int tap = s >> 3;
        const uint32_t coff = (uint32_t)(tap * (XS_STRIDE * 2) + (s & 7) * 32);
        uint32_t a0, a1, a2, a3, a4, a5, a6, a7;
        asm volatile("ldmatrix.sync.aligned.m8n8.x4.shared.b16 {%0,%1,%2,%3}, [%4];"
                     : "=r"(a0), "=r"(a1), "=r"(a2), "=r"(a3) : "r"(g.a_pre0 + coff));
        asm volatile("ldmatrix.sync.aligned.m8n8.x4.shared.b16 {%0,%1,%2,%3}, [%4];"
                     : "=r"(a4), "=r"(a5), "=r"(a6), "=r"(a7) : "r"(g.a_pre1 + coff));
        uint32_t b_addr = g.b_pre + (uint32_t)(s * 32);
        #pragma unroll
        for (int q = 0; q < 2; q++) {
            uint32_t b0, b1, b2, b3;
            asm volatile("ldmatrix.sync.aligned.m8n8.x4.shared.b16 {%0,%1,%2,%3}, [%4];"
                         : "=r"(b0), "=r"(b1), "=r"(b2), "=r"(b3) : "r"(b_addr));
            b_addr += 16u * BS_STRIDE * 2u;
            asm volatile("mma.sync.aligned.m16n8k16.row.col.f32.f16.f16.f32 "
                         "{%0,%1,%2,%3}, {%4,%5,%6,%7}, {%8,%9}, {%0,%1,%2,%3};"
                         : "+f"(d[0][2*q][0]), "+f"(d[0][2*q][1]),
                           "+f"(d[0][2*q][2]), "+f"(d[0][2*q][3])
                         : "r"(a0), "r"(a1), "r"(a2), "r"(a3), "r"(b0), "r"(b1));
            asm volatile("mma.sync.aligned.m16n8k16.row.col.f32.f16.f16.f32 "
                         "{%0,%1,%2,%3}, {%4,%5,%6,%7}, {%8,%9}, {%0,%1,%2,%3};"
                         : "+f"(d[0][2*q+1][0]), "+f"(d[0][2*q+1][1]),
                           "+f"(d[0][2*q+1][2]), "+f"(d[0][2*q+1][3])
                         : "r"(a0), "r"(a1), "r"(a2), "r"(a3), "r"(b2), "r"(b3));
            asm volatile("mma.sync.aligned.m16n8k16.row.col.f32.f16.f16.f32 "
                         "{%0,%1,%2,%3}, {%4,%5,%6,%7}, {%8,%9}, {%0,%1,%2,%3};"
                         : "+f"(d[1][2*q][0]), "+f"(d[1][2*q][1]),
                           "+f"(d[1][2*q][2]), "+f"(d[1][2*q][3])
                         : "r"(a4), "r"(a5), "r"(a6), "r"(a7), "r"(b0), "r"(b1));
            asm volatile("mma.sync.aligned.m16n8k16.row.col.f32.f16.f16.f32 "
                         "{%0,%1,%2,%3}, {%4,%5,%6,%7}, {%8,%9}, {%0,%1,%2,%3};"
                         : "+f"(d[1][2*q+1][0]), "+f"(d[1][2*q+1][1]),
                           "+f"(d[1][2*q+1][2]), "+f"(d[1][2*q+1][3])
                         : "r"(a4), "r"(a5), "r"(a6), "r"(a7), "r"(b2), "r"(b3));
        }
    }
}

__device__ __forceinline__ void t4_store(float (&d)[2][4][4], __half* t4s,
                                         int mt0, int cbase, int lane) {
    const int q0 = lane >> 2;
    const int tq = lane & 3;
    #pragma unroll
    for (int mi = 0; mi < 2; mi++) {
        const int rbase = (mt0 + mi) * 16;
        #pragma unroll
        for (int i = 0; i < 4; i++) {
            const int c0 = (cbase + i) * 8 + tq * 2;
            *(__half2*)(t4s + (rbase + q0) * T4_STRIDE + c0) =
                __floats2half2_rn(d[mi][i][0], d[mi][i][1]);
            *(__half2*)(t4s + (rbase + q0 + 8) * T4_STRIDE + c0) =
                __floats2half2_rn(d[mi][i][2], d[mi][i][3]);
        }
    }
}

// Incremental-index epilogue: walks i = tid + 1024*it over 25088 elements,
// maintaining (cl, p, b) with adds/wraps only. 1024 = 5*196+44, 44 = 3*14+2.
__device__ __forceinline__ void epilogue(const __half* t4s, const float2* w1v,
                                         float* om, int tid, int w1off) {
    int cl = tid / 196;
    int rr = tid - cl * 196;
    int p  = rr / 14;
    int b  = rr - p * 14;
    for (int i = tid; i < 25088; i += 1024) {
        int l1 = (p == 0) ? 13 : p - 1;
        int l2 = (p < 2) ? p + 12 : p - 2;
        float2 wv = w1v[w1off + cl];
        float v = wv.x * __half2float(t4s[(l1 * 16 + 1 + b) * T4_STRIDE + cl])
                + wv.y * __half2float(t4s[(l2 * 16 + 1 + b) * T4_STRIDE + cl]);
        om[i] = v;
        cl += 5; p += 3; b += 2;
        if (b >= 14) { b -= 14; p += 1; }
        if (p >= 14) { p -= 14; cl += 1; }
    }
}

__global__ __launch_bounds__(NT, 1) void kMain(const float* __restrict__ x,
                                               const float* __restrict__ w1,
                                               float* __restrict__ out) {
    extern __shared__ char smem[];
    __half* xs  = (__half*)(smem + XS_OFF);
    __half* Bs  = (__half*)(smem + BS_OFF);
    __half* t4s = (__half*)(smem + T4_OFF);

    const int tid  = threadIdx.x;
    const int m    = blockIdx.x;
    const int wid  = tid >> 5;
    const int lane = tid & 31;

    // ================= Phase A: zero pads + build xs + load Bs(0) ==========
    {   // rows u%16 in {0,1} (28 rows) plus rows 224,225 (r=28,29)
        uint32_t* xz = (uint32_t*)xs;
        for (int i = tid; i < 30 * 64; i += NT) {
            int r   = i >> 6;
            int row = (r >> 1) * 16 + (r & 1);
            xz[(row * XS_STRIDE) / 2 + (i & 63)] = 0;
        }
    }
    {   // build xs with incremental (j, l, h) tracking
        const float* xm = x + (size_t)m * 25088;
        int j = tid / 196;
        int lh = tid - j * 196;
        int l  = lh / 14;
        int h  = lh - l * 14;
        for (int i = tid; i < 25088; i += 1024) {
            xs[(l * 16 + h + 2) * XS_STRIDE + j] = __float2half(xm[i]);
            j += 5; l += 3; h += 2;
            if (h >= 14) { h -= 14; l += 1; }
            if (l >= 14) { l -= 14; j += 1; }
        }
    }
    {
        const uint32_t* src = (const uint32_t*)g_Bh;          // hc=0
        for (int i = tid; i < 128 * 192; i += NT) {
            int c  = i / 192;
            int kw = i - c * 192;
            *(uint32_t*)(Bs + c * BS_STRIDE + kw * 2) = src[i];
        }
    }

    // ---- per-warp constants: 28 active warps = 7 m-pairs x 4 n32-groups ----
    const bool active = wid < 28;
    const int  mpair  = active ? (wid % 7) : 0;
    const int  ngrp   = active ? (wid / 7) : 0;    // 0..3
    const int  mt0    = mpair * 2;
    const int  cbase  = ngrp * 4;                  // first n8-tile

    GemmCtx g;
    g.active = active;
    g.a_pre0 = smem_u32(xs) +
        (uint32_t)(((mt0 * 16 + (lane & 15)) * XS_STRIDE + ((lane >> 4) << 3)) * 2);
    g.a_pre1 = g.a_pre0 + (uint32_t)(16 * XS_STRIDE * 2);
    {
        const int n_in16 = (((lane >> 4) & 1) << 3) + (lane & 7);
        const int k_half = ((lane >> 3) & 1) << 3;
        g.b_pre = smem_u32(Bs) +
            (uint32_t)(((cbase * 8 + n_in16) * BS_STRIDE + k_half) * 2);
    }

    float* om = out + (size_t)m * 50176;
    const float2* w1v = (const float2*)w1;

    float d[2][4][4];
    __syncthreads();

    // ================= hc = 0 ==============================================
    gemm_phase(d, g);
    __syncthreads();

    // t4s store(0) + Bs(1) load
    if (active) t4_store(d, t4s, mt0, cbase, lane);
    {
        const uint32_t* src = (const uint32_t*)(g_Bh + 128 * 384);   // hc=1
        for (int i = tid; i < 128 * 192; i += NT) {
            int c  = i / 192;
            int kw = i - c * 192;
            *(uint32_t*)(Bs + c * BS_STRIDE + kw * 2) = src[i];
        }
    }
    __syncthreads();

    // epilogue(0) then gemm(1); disjoint read sets (t4s vs xs/Bs), no barrier
    epilogue(t4s, w1v, om, tid, 0);
    gemm_phase(d, g);
    __syncthreads();

    // t4s store(1)
    if (active) t4_store(d, t4s, mt0, cbase, lane);
    __syncthreads();

    // epilogue(1)
    epilogue(t4s, w1v, om + 25088, tid, 128);
}

// ===========================================================================
extern "C" void kernel_launch(void* const* d_in, const int* in_sizes, int n_in,
                              void* d_out, int out_size) {
    const float* x  = (const float*)d_in[0];   // (1024, 1792, 14)
    const float* w1 = (const float*)d_in[1];   // (256, 2)
    const float* w2 = (const float*)d_in[2];   // (128, 3, 256)
    float* out = (float*)d_out;                // (1024, 256, 14, 14)

    static int attr_done = 0;
    if (!attr_done) {
        cudaFuncSetAttribute(kMain, cudaFuncAttributeMaxDynamicSharedMemorySize,
                             SMEM_BYTES);
        attr_done = 1;
    }

    kB<<<384, 256>>>(w2);
    kMain<<<1024, NT, SMEM_BYTES>>>(x, w1, out);
}

// round 14
// speedup vs baseline: 1.5537x; 1.0704x over previous
#include <cuda_runtime.h>
#include <cuda_fp16.h>
#include <cstdint>

// ===========================================================================
// One CTA per m, 1024 threads = 32 warps (28 active in GEMM), warp m32 x n32.
// Warp w: mpair = w%7 -> m-tiles (2*mpair, 2*mpair+1); ngrp = w/7 (0..3) ->
// n8-tiles [ngrp*4, ngrp*4+4) = 32 channels. 2.0 smem-wavefronts per MMA.
// GEMM rows grouped by l: l-tile covers rows q=0..15 (q=1..14 <-> n=q-1).
// xs[u][j]: u = l*16 + h + 2; rows u%16 in {0,1} and 224/225 are zero pads,
// written EVERY launch (uninit smem diverges across graph replays).
// R14: xs built via row-wise STS.128 (conflict-free; was 4-way U16 stores).
// t4s stride = 138 halves (69 words, odd) -> epilogue LDS conflict-free.
// Phasing (6 barriers): build+Bs0 | gemm0 | t4s0+Bs1 | epi0;gemm1 | t4s1 | epi1
// ===========================================================================

__device__ __align__(16) __half g_Bh[256 * 384];   // [c][kk], kk = k*128+j

__device__ __forceinline__ uint32_t smem_u32(const void* p) {
    uint32_t a;
    asm("{ .reg .u64 t; cvta.to.shared.u64 t, %1; cvt.u32.u64 %0, t; }" : "=r"(a) : "l"(p));
    return a;
}

__global__ __launch_bounds__(256) void kB(const float* __restrict__ w2) {
    int i = blockIdx.x * 256 + threadIdx.x;          // 98304 total
    if (i >= 98304) return;
    int c  = i / 384;
    int kk = i - c * 384;
    int k  = kk >> 7;
    int j  = kk & 127;
    g_Bh[i] = __float2half(w2[j * 768 + k * 256 + c]);
}

static constexpr int XS_STRIDE = 136;   // halves (272B rows; ldsm conflict-free)
static constexpr int BS_STRIDE = 392;   // halves (784B rows; ldsm conflict-free)
static constexpr int T4_STRIDE = 138;   // halves (69 words, odd -> conflict-free)

static constexpr int XS_OFF = 0;                      // 226*136*2 = 61472 B
static constexpr int BS_OFF = 61472;                  // 128*392*2 = 100352 B
static constexpr int T4_OFF = 161824;                 // 224*138*2 = 61824 B
static constexpr int SMEM_BYTES = 223648;

static constexpr int NT = 1024;         // 32 warps; 28 active in GEMM

struct GemmCtx { uint32_t a_pre0, a_pre1, b_pre; bool active; };

__device__ __forceinline__ void gemm_phase(float (&d)[2][4][4], const GemmCtx& g) {
    #pragma unroll
    for (int mi = 0; mi < 2; mi++)
        #pragma unroll
        for (int i = 0; i < 4; i++)
            #pragma unroll
            for (int q = 0; q < 4; q++) d[mi][i][q] = 0.f;
    if (!g.active) return;
    #pragma unroll 4
    for (int s = 0; s < 24; s++) {
        const int tap = s >> 3;
        const uint32_t coff = (uint32_t)(tap * (XS_STRIDE * 2) + (s & 7) * 32);
        uint32_t a0, a1, a2, a3, a4, a5, a6, a7;
        asm volatile("ldmatrix.sync.aligned.m8n8.x4.shared.b16 {%0,%1,%2,%3}, [%4];"
                     : "=r"(a0), "=r"(a1), "=r"(a2), "=r"(a3) : "r"(g.a_pre0 + coff));
        asm volatile("ldmatrix.sync.aligned.m8n8.x4.shared.b16 {%0,%1,%2,%3}, [%4];"
                     : "=r"(a4), "=r"(a5), "=r"(a6), "=r"(a7) : "r"(g.a_pre1 + coff));
        uint32_t b_addr = g.b_pre + (uint32_t)(s * 32);
        #pragma unroll
        for (int q = 0; q < 2; q++) {
            uint32_t b0, b1, b2, b3;
            asm volatile("ldmatrix.sync.aligned.m8n8.x4.shared.b16 {%0,%1,%2,%3}, [%4];"
                         : "=r"(b0), "=r"(b1), "=r"(b2), "=r"(b3) : "r"(b_addr));
            b_addr += 16u * BS_STRIDE * 2u;
            asm volatile("mma.sync.aligned.m16n8k16.row.col.f32.f16.f16.f32 "
                         "{%0,%1,%2,%3}, {%4,%5,%6,%7}, {%8,%9}, {%0,%1,%2,%3};"
                         : "+f"(d[0][2*q][0]), "+f"(d[0][2*q][1]),
                           "+f"(d[0][2*q][2]), "+f"(d[0][2*q][3])
                         : "r"(a0), "r"(a1), "r"(a2), "r"(a3), "r"(b0), "r"(b1));
            asm volatile("mma.sync.aligned.m16n8k16.row.col.f32.f16.f16.f32 "
                         "{%0,%1,%2,%3}, {%4,%5,%6,%7}, {%8,%9}, {%0,%1,%2,%3};"
                         : "+f"(d[0][2*q+1][0]), "+f"(d[0][2*q+1][1]),
                           "+f"(d[0][2*q+1][2]), "+f"(d[0][2*q+1][3])
                         : "r"(a0), "r"(a1), "r"(a2), "r"(a3), "r"(b2), "r"(b3));
            asm volatile("mma.sync.aligned.m16n8k16.row.col.f32.f16.f16.f32 "
                         "{%0,%1,%2,%3}, {%4,%5,%6,%7}, {%8,%9}, {%0,%1,%2,%3};"
                         : "+f"(d[1][2*q][0]), "+f"(d[1][2*q][1]),
                           "+f"(d[1][2*q][2]), "+f"(d[1][2*q][3])
                         : "r"(a4), "r"(a5), "r"(a6), "r"(a7), "r"(b0), "r"(b1));
            asm volatile("mma.sync.aligned.m16n8k16.row.col.f32.f16.f16.f32 "
                         "{%0,%1,%2,%3}, {%4,%5,%6,%7}, {%8,%9}, {%0,%1,%2,%3};"
                         : "+f"(d[1][2*q+1][0]), "+f"(d[1][2*q+1][1]),
                           "+f"(d[1][2*q+1][2]), "+f"(d[1][2*q+1][3])
                         : "r"(a4), "r"(a5), "r"(a6), "r"(a7), "r"(b2), "r"(b3));
        }
    }
}

__device__ __forceinline__ void t4_store(float (&d)[2][4][4], __half* t4s,
                                         int mt0, int cbase, int lane) {
    const int q0 = lane >> 2;
    const int tq = lane & 3;
    #pragma unroll
    for (int mi = 0; mi < 2; mi++) {
        const int rbase = (mt0 + mi) * 16;
        #pragma unroll
        for (int i = 0; i < 4; i++) {
            const int c0 = (cbase + i) * 8 + tq * 2;
            *(__half2*)(t4s + (rbase + q0) * T4_STRIDE + c0) =
                __floats2half2_rn(d[mi][i][0], d[mi][i][1]);
            *(__half2*)(t4s + (rbase + q0 + 8) * T4_STRIDE + c0) =
                __floats2half2_rn(d[mi][i][2], d[mi][i][3]);
        }
    }
}

// Incremental-index epilogue: walks i = tid + 1024*it over 25088 elements.
__device__ __forceinline__ void epilogue(const __half* t4s, const float2* w1v,
                                         float* om, int tid, int w1off) {
    int cl = tid / 196;
    int rr = tid - cl * 196;
    int p  = rr / 14;
    int b  = rr - p * 14;
    for (int i = tid; i < 25088; i += 1024) {
        int l1 = (p == 0) ? 13 : p - 1;
        int l2 = (p < 2) ? p + 12 : p - 2;
        float2 wv = w1v[w1off + cl];
        float v = wv.x * __half2float(t4s[(l1 * 16 + 1 + b) * T4_STRIDE + cl])
                + wv.y * __half2float(t4s[(l2 * 16 + 1 + b) * T4_STRIDE + cl]);
        om[i] = v;
        cl += 5; p += 3; b += 2;
        if (b >= 14) { b -= 14; p += 1; }
        if (p >= 14) { p -= 14; cl += 1; }
    }
}

// Bs half (128 c-rows x 384 halves = 48 uint4/row) -> smem, uint4 copies.
__device__ __forceinline__ void bs_load(char* smem_base, const uint4* src, int tid) {
    int c = tid / 48;
    int w = tid - c * 48;
    #pragma unroll
    for (int it = 0; it < 6; it++) {               // 6144 uint4 total
        *(uint4*)(smem_base + c * 784 + w * 16) = src[c * 48 + w];
        c += 21; w += 16;                          // +1024 = 21*48 + 16
        if (w >= 48) { w -= 48; c += 1; }
    }
}

__global__ __launch_bounds__(NT, 1) void kMain(const float* __restrict__ x,
                                               const float* __restrict__ w1,
                                               float* __restrict__ out) {
    extern __shared__ char smem[];
    __half* xs  = (__half*)(smem + XS_OFF);
    char*   bsb = smem + BS_OFF;
    __half* t4s = (__half*)(smem + T4_OFF);

    const int tid  = threadIdx.x;
    const int m    = blockIdx.x;
    const int wid  = tid >> 5;
    const int lane = tid & 31;

    // ===== Phase A: build xs via STS.128 (pads zeroed in-loop) + Bs0 =======
    {
        const float* xm = x + (size_t)m * 25088;
        int u  = tid % 226;          // row
        int jb = tid / 226;          // 16B block (8 halves) within row
        #pragma unroll
        for (int it = 0; it < 4; it++) {            // covers 226*16 = 3616 slots
            if (jb < 16) {
                uint4 v = make_uint4(0u, 0u, 0u, 0u);
                const int q = u & 15;
                if (q >= 2 && u < 224) {
                    const float* src = xm + ((u >> 4) * 14 + q - 2);
                    float f0 = src[(jb * 8 + 0) * 196];
                    float f1 = src[(jb * 8 + 1) * 196];
                    float f2 = src[(jb * 8 + 2) * 196];
                    float f3 = src[(jb * 8 + 3) * 196];
                    float f4 = src[(jb * 8 + 4) * 196];
                    float f5 = src[(jb * 8 + 5) * 196];
                    float f6 = src[(jb * 8 + 6) * 196];
                    float f7 = src[(jb * 8 + 7) * 196];
                    __half2 h0 = __floats2half2_rn(f0, f1);
                    __half2 h1 = __floats2half2_rn(f2, f3);
                    __half2 h2 = __floats2half2_rn(f4, f5);
                    __half2 h3 = __floats2half2_rn(f6, f7);
                    v.x = *(uint32_t*)&h0; v.y = *(uint32_t*)&h1;
                    v.z = *(uint32_t*)&h2; v.w = *(uint32_t*)&h3;
                }
                *(uint4*)((char*)xs + u * (XS_STRIDE * 2) + jb * 16) = v;
            }
            u += 120; jb += 4;                      // +1024 = 4*226 + 120
            if (u >= 226) { u -= 226; jb += 1; }
        }
    }
    bs_load(bsb, (const uint4*)g_Bh, tid);          // hc=0

    // ---- per-warp constants: 28 active warps = 7 m-pairs x 4 n32-groups ----
    const bool active = wid < 28;
    const int  mpair  = active ? (wid % 7) : 0;
    const int  ngrp   = active ? (wid / 7) : 0;    // 0..3
    const int  mt0    = mpair * 2;
    const int  cbase  = ngrp * 4;                  // first n8-tile

    GemmCtx g;
    g.active = active;
    g.a_pre0 = smem_u32(xs) +
        (uint32_t)(((mt0 * 16 + (lane & 15)) * XS_STRIDE + ((lane >> 4) << 3)) * 2);
    g.a_pre1 = g.a_pre0 + (uint32_t)(16 * XS_STRIDE * 2);
    {
        const int n_in16 = (((lane >> 4) & 1) << 3) + (lane & 7);
        const int k_half = ((lane >> 3) & 1) << 3;
        g.b_pre = smem_u32(bsb) +
            (uint32_t)(((cbase * 8 + n_in16) * BS_STRIDE + k_half) * 2);
    }

    float* om = out + (size_t)m * 50176;
    const float2* w1v = (const float2*)w1;

    float d[2][4][4];
    __syncthreads();

    // ================= hc = 0 ==============================================
    gemm_phase(d, g);
    __syncthreads();

    // t4s store(0) + Bs(1) load
    if (active) t4_store(d, t4s, mt0, cbase, lane);
    bs_load(bsb, (const uint4*)(g_Bh + 128 * 384), tid);    // hc=1
    __syncthreads();

    // epilogue(0) then gemm(1); disjoint read sets (t4s vs xs/Bs), no barrier
    epilogue(t4s, w1v, om, tid, 0);
    gemm_phase(d, g);
    __syncthreads();

    // t4s store(1)
    if (active) t4_store(d, t4s, mt0, cbase, lane);
    __syncthreads();

    // epilogue(1)
    epilogue(t4s, w1v, om + 25088, tid, 128);
}

// ===========================================================================
extern "C" void kernel_launch(void* const* d_in, const int* in_sizes, int n_in,
                              void* d_out, int out_size) {
    const float* x  = (const float*)d_in[0];   // (1024, 1792, 14)
    const float* w1 = (const float*)d_in[1];   // (256, 2)
    const float* w2 = (const float*)d_in[2];   // (128, 3, 256)
    float* out = (float*)d_out;                // (1024, 256, 14, 14)

    static int attr_done = 0;
    if (!attr_done) {
        cudaFuncSetAttribute(kMain, cudaFuncAttributeMaxDynamicSharedMemorySize,
                             SMEM_BYTES);
        attr_done = 1;
    }

    kB<<<384, 256>>>(w2);
    kMain<<<1024, NT, SMEM_BYTES>>>(x, w1, out);
}

// round 15
// speedup vs baseline: 1.6618x; 1.0695x over previous
#include <cuda_runtime.h>
#include <cuda_fp16.h>
#include <cstdint>

// ===========================================================================
// One CTA per m, 896 threads = 28 warps (all active), warp m32 x n32.
// Warp w: mpair = w%7 -> m-tiles (2*mpair, 2*mpair+1); ngrp = w/7 (0..3) ->
// n8-tiles [ngrp*4, ngrp*4+4) = 32 channels. 2.0 smem-wavefronts per MMA.
// GEMM rows grouped by l: l-tile covers rows q=0..15 (q=1..14 <-> n=q-1).
// xs[u][j]: u = l*16 + h + 2; rows u%16 in {0,1} and 224/225 are zero pads,
// written EVERY launch (uninit smem diverges across graph replays).
// t4s stride = 138 halves (69 words, odd) -> epilogue LDS conflict-free.
// Phasing: build+bs0 | gemm0;t4s0 | bs1 | epi0;gemm1 | t4s1 | epi1
// (t4s0 folded into gemm0 phase: t4s writes are disjoint from xs/Bs reads.)
// ===========================================================================

__device__ __align__(16) __half g_Bh[256 * 384];   // [c][kk], kk = k*128+j

__device__ __forceinline__ uint32_t smem_u32(const void* p) {
    uint32_t a;
    asm("{ .reg .u64 t; cvta.to.shared.u64 t, %1; cvt.u32.u64 %0, t; }" : "=r"(a) : "l"(p));
    return a;
}

__global__ __launch_bounds__(256) void kB(const float* __restrict__ w2) {
    int i = blockIdx.x * 256 + threadIdx.x;          // 98304 total
    if (i >= 98304) return;
    int c  = i / 384;
    int kk = i - c * 384;
    int k  = kk >> 7;
    int j  = kk & 127;
    g_Bh[i] = __float2half(w2[j * 768 + k * 256 + c]);
}

static constexpr int XS_STRIDE = 136;   // halves (272B rows; ldsm conflict-free)
static constexpr int BS_STRIDE = 392;   // halves (784B rows; ldsm conflict-free)
static constexpr int T4_STRIDE = 138;   // halves (69 words, odd -> conflict-free)

static constexpr int XS_OFF = 0;                      // 226*136*2 = 61472 B
static constexpr int BS_OFF = 61472;                  // 128*392*2 = 100352 B
static constexpr int T4_OFF = 161824;                 // 224*138*2 = 61824 B
static constexpr int SMEM_BYTES = 223648;

static constexpr int NT = 896;          // 28 warps, all active in GEMM

struct GemmCtx { uint32_t a_pre0, a_pre1, b_pre; };

__device__ __forceinline__ void gemm_phase(float (&d)[2][4][4], const GemmCtx& g) {
    #pragma unroll
    for (int mi = 0; mi < 2; mi++)
        #pragma unroll
        for (int i = 0; i < 4; i++)
            #pragma unroll
            for (int q = 0; q < 4; q++) d[mi][i][q] = 0.f;
    #pragma unroll 4
    for (int s = 0; s < 24; s++) {
        const int tap = s >> 3;
        const uint32_t coff = (uint32_t)(tap * (XS_STRIDE * 2) + (s & 7) * 32);
        uint32_t a0, a1, a2, a3, a4, a5, a6, a7;
        asm volatile("ldmatrix.sync.aligned.m8n8.x4.shared.b16 {%0,%1,%2,%3}, [%4];"
                     : "=r"(a0), "=r"(a1), "=r"(a2), "=r"(a3) : "r"(g.a_pre0 + coff));
        asm volatile("ldmatrix.sync.aligned.m8n8.x4.shared.b16 {%0,%1,%2,%3}, [%4];"
                     : "=r"(a4), "=r"(a5), "=r"(a6), "=r"(a7) : "r"(g.a_pre1 + coff));
        uint32_t b_addr = g.b_pre + (uint32_t)(s * 32);
        #pragma unroll
        for (int q = 0; q < 2; q++) {
            uint32_t b0, b1, b2, b3;
            asm volatile("ldmatrix.sync.aligned.m8n8.x4.shared.b16 {%0,%1,%2,%3}, [%4];"
                         : "=r"(b0), "=r"(b1), "=r"(b2), "=r"(b3) : "r"(b_addr));
            b_addr += 16u * BS_STRIDE * 2u;
            asm volatile("mma.sync.aligned.m16n8k16.row.col.f32.f16.f16.f32 "
                         "{%0,%1,%2,%3}, {%4,%5,%6,%7}, {%8,%9}, {%0,%1,%2,%3};"
                         : "+f"(d[0][2*q][0]), "+f"(d[0][2*q][1]),
                           "+f"(d[0][2*q][2]), "+f"(d[0][2*q][3])
                         : "r"(a0), "r"(a1), "r"(a2), "r"(a3), "r"(b0), "r"(b1));
            asm volatile("mma.sync.aligned.m16n8k16.row.col.f32.f16.f16.f32 "
                         "{%0,%1,%2,%3}, {%4,%5,%6,%7}, {%8,%9}, {%0,%1,%2,%3};"
                         : "+f"(d[0][2*q+1][0]), "+f"(d[0][2*q+1][1]),
                           "+f"(d[0][2*q+1][2]), "+f"(d[0][2*q+1][3])
                         : "r"(a0), "r"(a1), "r"(a2), "r"(a3), "r"(b2), "r"(b3));
            asm volatile("mma.sync.aligned.m16n8k16.row.col.f32.f16.f16.f32 "
                         "{%0,%1,%2,%3}, {%4,%5,%6,%7}, {%8,%9}, {%0,%1,%2,%3};"
                         : "+f"(d[1][2*q][0]), "+f"(d[1][2*q][1]),
                           "+f"(d[1][2*q][2]), "+f"(d[1][2*q][3])
                         : "r"(a4), "r"(a5), "r"(a6), "r"(a7), "r"(b0), "r"(b1));
            asm volatile("mma.sync.aligned.m16n8k16.row.col.f32.f16.f16.f32 "
                         "{%0,%1,%2,%3}, {%4,%5,%6,%7}, {%8,%9}, {%0,%1,%2,%3};"
                         : "+f"(d[1][2*q+1][0]), "+f"(d[1][2*q+1][1]),
                           "+f"(d[1][2*q+1][2]), "+f"(d[1][2*q+1][3])
                         : "r"(a4), "r"(a5), "r"(a6), "r"(a7), "r"(b2), "r"(b3));
        }
    }
}

__device__ __forceinline__ void t4_store(float (&d)[2][4][4], __half* t4s,
                                         int mt0, int cbase, int lane) {
    const int q0 = lane >> 2;
    const int tq = lane & 3;
    #pragma unroll
    for (int mi = 0; mi < 2; mi++) {
        const int rbase = (mt0 + mi) * 16;
        #pragma unroll
        for (int i = 0; i < 4; i++) {
            const int c0 = (cbase + i) * 8 + tq * 2;
            *(__half2*)(t4s + (rbase + q0) * T4_STRIDE + c0) =
                __floats2half2_rn(d[mi][i][0], d[mi][i][1]);
            *(__half2*)(t4s + (rbase + q0 + 8) * T4_STRIDE + c0) =
                __floats2half2_rn(d[mi][i][2], d[mi][i][3]);
        }
    }
}

// Incremental epilogue: i = tid + 896*it over 25088 elements (28 iters exact).
// 896 = 4*196 + 112; 112 = 8*14 -> cl += 4, p += 8, b invariant.
__device__ __forceinline__ void epilogue(const __half* t4s, const float2* w1v,
                                         float* om, int tid, int w1off) {
    int cl = tid / 196;
    int rr = tid - cl * 196;
    int p  = rr / 14;
    int b  = rr - p * 14;
    #pragma unroll 4
    for (int i = tid; i < 25088; i += NT) {
        int l1 = (p == 0) ? 13 : p - 1;
        int l2 = (p < 2) ? p + 12 : p - 2;
        float2 wv = w1v[w1off + cl];
        float v = wv.x * __half2float(t4s[(l1 * 16 + 1 + b) * T4_STRIDE + cl])
                + wv.y * __half2float(t4s[(l2 * 16 + 1 + b) * T4_STRIDE + cl]);
        om[i] = v;
        cl += 4; p += 8;
        if (p >= 14) { p -= 14; cl += 1; }
    }
}

// Bs half (128 c-rows x 384 halves = 48 uint4/row) -> smem, uint4 copies.
// 896 = 18*48 + 32; 7 iterations cover 6144 uint4 (guard on last).
__device__ __forceinline__ void bs_load(char* smem_base, const uint4* src, int tid) {
    int c = tid / 48;
    int w = tid - c * 48;
    #pragma unroll
    for (int it = 0; it < 7; it++) {
        if (c < 128) *(uint4*)(smem_base + c * 784 + w * 16) = src[c * 48 + w];
        c += 18; w += 32;
        if (w >= 48) { w -= 48; c += 1; }
    }
}

__global__ __launch_bounds__(NT, 1) void kMain(const float* __restrict__ x,
                                               const float* __restrict__ w1,
                                               float* __restrict__ out) {
    extern __shared__ char smem[];
    __half* xs  = (__half*)(smem + XS_OFF);
    char*   bsb = smem + BS_OFF;
    __half* t4s = (__half*)(smem + T4_OFF);

    const int tid  = threadIdx.x;
    const int m    = blockIdx.x;
    const int wid  = tid >> 5;
    const int lane = tid & 31;

    // ===== Phase A: build xs via STS.128 (pads zeroed in-loop) + Bs0 =======
    {
        const float* xm = x + (size_t)m * 25088;
        int u  = tid % 226;          // row
        int jb = tid / 226;          // 16B block (8 halves) within row
        #pragma unroll
        for (int it = 0; it < 5; it++) {            // covers 226*16 = 3616 slots
            if (jb < 16) {
                uint4 v = make_uint4(0u, 0u, 0u, 0u);
                const int q = u & 15;
                if (q >= 2 && u < 224) {
                    const float* src = xm + ((u >> 4) * 14 + q - 2);
                    float f0 = src[(jb * 8 + 0) * 196];
                    float f1 = src[(jb * 8 + 1) * 196];
                    float f2 = src[(jb * 8 + 2) * 196];
                    float f3 = src[(jb * 8 + 3) * 196];
                    float f4 = src[(jb * 8 + 4) * 196];
                    float f5 = src[(jb * 8 + 5) * 196];
                    float f6 = src[(jb * 8 + 6) * 196];
                    float f7 = src[(jb * 8 + 7) * 196];
                    __half2 h0 = __floats2half2_rn(f0, f1);
                    __half2 h1 = __floats2half2_rn(f2, f3);
                    __half2 h2 = __floats2half2_rn(f4, f5);
                    __half2 h3 = __floats2half2_rn(f6, f7);
                    v.x = *(uint32_t*)&h0; v.y = *(uint32_t*)&h1;
                    v.z = *(uint32_t*)&h2; v.w = *(uint32_t*)&h3;
                }
                *(uint4*)((char*)xs + u * (XS_STRIDE * 2) + jb * 16) = v;
            }
            u += 218; jb += 3;                      // +896 = 3*226 + 218
            if (u >= 226) { u -= 226; jb += 1; }
        }
    }
    bs_load(bsb, (const uint4*)g_Bh, tid);          // hc=0

    // ---- per-warp constants: 28 warps = 7 m-pairs x 4 n32-groups ----
    const int  mpair  = wid % 7;
    const int  ngrp   = wid / 7;                   // 0..3
    const int  mt0    = mpair * 2;
    const int  cbase  = ngrp * 4;                  // first n8-tile

    GemmCtx g;
    g.a_pre0 = smem_u32(xs) +
        (uint32_t)(((mt0 * 16 + (lane & 15)) * XS_STRIDE + ((lane >> 4) << 3)) * 2);
    g.a_pre1 = g.a_pre0 + (uint32_t)(16 * XS_STRIDE * 2);
    {
        const int n_in16 = (((lane >> 4) & 1) << 3) + (lane & 7);
        const int k_half = ((lane >> 3) & 1) << 3;
        g.b_pre = smem_u32(bsb) +
            (uint32_t)(((cbase * 8 + n_in16) * BS_STRIDE + k_half) * 2);
    }

    float* om = out + (size_t)m * 50176;
    const float2* w1v = (const float2*)w1;

    float d[2][4][4];
    __syncthreads();

    // ===== gemm(0) + t4s store(0) folded (t4s disjoint from xs/Bs reads) ===
    gemm_phase(d, g);
    t4_store(d, t4s, mt0, cbase, lane);
    __syncthreads();   // t4s0 complete; Bs0 reads complete

    // ===== Bs(1) load (own short phase) =====================================
    bs_load(bsb, (const uint4*)(g_Bh + 128 * 384), tid);    // hc=1
    __syncthreads();

    // ===== epilogue(0) then gemm(1); disjoint read sets, no barrier ========
    epilogue(t4s, w1v, om, tid, 0);
    gemm_phase(d, g);
    __syncthreads();   // epi0 t4s reads complete before t4s1 overwrite

    // ===== t4s store(1) =====================================================
    t4_store(d, t4s, mt0, cbase, lane);
    __syncthreads();

    // ===== epilogue(1) ======================================================
    epilogue(t4s, w1v, om + 25088, tid, 128);
}

// ===========================================================================
extern "C" void kernel_launch(void* const* d_in, const int* in_sizes, int n_in,
                              void* d_out, int out_size) {
    const float* x  = (const float*)d_in[0];   // (1024, 1792, 14)
    const float* w1 = (const float*)d_in[1];   // (256, 2)
    const float* w2 = (const float*)d_in[2];   // (128, 3, 256)
    float* out = (float*)d_out;                // (1024, 256, 14, 14)

    static int attr_done = 0;
    if (!attr_done) {
        cudaFuncSetAttribute(kMain, cudaFuncAttributeMaxDynamicSharedMemorySize,
                             SMEM_BYTES);
        attr_done = 1;
    }

    kB<<<384, 256>>>(w2);
    kMain<<<1024, NT, SMEM_BYTES>>>(x, w1, out);
}

// round 16
// speedup vs baseline: 1.6664x; 1.0028x over previous
#include <cuda_runtime.h>
#include <cuda_fp16.h>
#include <cstdint>

// ===========================================================================
// One CTA per m, 896 threads = 28 warps (all active), warp m32 x n32.
// Warp w: mpair = w%7 -> m-tiles (2*mpair, 2*mpair+1); ngrp = w/7 (0..3) ->
// n8-tiles [ngrp*4, ngrp*4+4) = 32 channels. 2.0 smem-wavefronts per MMA.
// GEMM rows grouped by l: l-tile covers rows q=0..15 (q=1..14 <-> n=q-1).
// xs[u][j]: u = l*16 + h + 2; rows u%16 in {0,1} and 224/225 are zero pads,
// written EVERY launch (uninit smem diverges across graph replays).
// t4s stride = 138 halves (69 words, odd) -> epilogue LDS conflict-free.
// Phasing: build+bs0 | gemm0;t4s0 | bs1 | epi0;gemm1 | t4s1 | epi1
// (t4s0 folded into gemm0 phase: t4s writes are disjoint from xs/Bs reads.)
// ===========================================================================

__device__ __align__(16) __half g_Bh[256 * 384];   // [c][kk], kk = k*128+j

__device__ __forceinline__ uint32_t smem_u32(const void* p) {
    uint32_t a;
    asm("{ .reg .u64 t; cvta.to.shared.u64 t, %1; cvt.u32.u64 %0, t; }" : "=r"(a) : "l"(p));
    return a;
}

__global__ __launch_bounds__(256) void kB(const float* __restrict__ w2) {
    int i = blockIdx.x * 256 + threadIdx.x;          // 98304 total
    if (i >= 98304) return;
    int c  = i / 384;
    int kk = i - c * 384;
    int k  = kk >> 7;
    int j  = kk & 127;
    g_Bh[i] = __float2half(w2[j * 768 + k * 256 + c]);
}

static constexpr int XS_STRIDE = 136;   // halves (272B rows; ldsm conflict-free)
static constexpr int BS_STRIDE = 392;   // halves (784B rows; ldsm conflict-free)
static constexpr int T4_STRIDE = 138;   // halves (69 words, odd -> conflict-free)

static constexpr int XS_OFF = 0;                      // 226*136*2 = 61472 B
static constexpr int BS_OFF = 61472;                  // 128*392*2 = 100352 B
static constexpr int T4_OFF = 161824;                 // 224*138*2 = 61824 B
static constexpr int SMEM_BYTES = 223648;

static constexpr int NT = 896;          // 28 warps, all active in GEMM

struct GemmCtx { uint32_t a_pre0, a_pre1, b_pre; };

__device__ __forceinline__ void gemm_phase(float (&d)[2][4][4], const GemmCtx& g) {
    #pragma unroll
    for (int mi = 0; mi < 2; mi++)
        #pragma unroll
        for (int i = 0; i < 4; i++)
            #pragma unroll
            for (int q = 0; q < 4; q++) d[mi][i][q] = 0.f;
    #pragma unroll 4
    for (int s = 0; s < 24; s++) {
        const int tap = s >> 3;
        const uint32_t coff = (uint32_t)(tap * (XS_STRIDE * 2) + (s & 7) * 32);
        uint32_t a0, a1, a2, a3, a4, a5, a6, a7;
        asm volatile("ldmatrix.sync.aligned.m8n8.x4.shared.b16 {%0,%1,%2,%3}, [%4];"
                     : "=r"(a0), "=r"(a1), "=r"(a2), "=r"(a3) : "r"(g.a_pre0 + coff));
        asm volatile("ldmatrix.sync.aligned.m8n8.x4.shared.b16 {%0,%1,%2,%3}, [%4];"
                     : "=r"(a4), "=r"(a5), "=r"(a6), "=r"(a7) : "r"(g.a_pre1 + coff));
        uint32_t b_addr = g.b_pre + (uint32_t)(s * 32);
        #pragma unroll
        for (int q = 0; q < 2; q++) {
            uint32_t b0, b1, b2, b3;
            asm volatile("ldmatrix.sync.aligned.m8n8.x4.shared.b16 {%0,%1,%2,%3}, [%4];"
                         : "=r"(b0), "=r"(b1), "=r"(b2), "=r"(b3) : "r"(b_addr));
            b_addr += 16u * BS_STRIDE * 2u;
            asm volatile("mma.sync.aligned.m16n8k16.row.col.f32.f16.f16.f32 "
                         "{%0,%1,%2,%3}, {%4,%5,%6,%7}, {%8,%9}, {%0,%1,%2,%3};"
                         : "+f"(d[0][2*q][0]), "+f"(d[0][2*q][1]),
                           "+f"(d[0][2*q][2]), "+f"(d[0][2*q][3])
                         : "r"(a0), "r"(a1), "r"(a2), "r"(a3), "r"(b0), "r"(b1));
            asm volatile("mma.sync.aligned.m16n8k16.row.col.f32.f16.f16.f32 "
                         "{%0,%1,%2,%3}, {%4,%5,%6,%7}, {%8,%9}, {%0,%1,%2,%3};"
                         : "+f"(d[0][2*q+1][0]), "+f"(d[0][2*q+1][1]),
                           "+f"(d[0][2*q+1][2]), "+f"(d[0][2*q+1][3])
                         : "r"(a0), "r"(a1), "r"(a2), "r"(a3), "r"(b2), "r"(b3));
            asm volatile("mma.sync.aligned.m16n8k16.row.col.f32.f16.f16.f32 "
                         "{%0,%1,%2,%3}, {%4,%5,%6,%7}, {%8,%9}, {%0,%1,%2,%3};"
                         : "+f"(d[1][2*q][0]), "+f"(d[1][2*q][1]),
                           "+f"(d[1][2*q][2]), "+f"(d[1][2*q][3])
                         : "r"(a4), "r"(a5), "r"(a6), "r"(a7), "r"(b0), "r"(b1));
            asm volatile("mma.sync.aligned.m16n8k16.row.col.f32.f16.f16.f32 "
                         "{%0,%1,%2,%3}, {%4,%5,%6,%7}, {%8,%9}, {%0,%1,%2,%3};"
                         : "+f"(d[1][2*q+1][0]), "+f"(d[1][2*q+1][1]),
                           "+f"(d[1][2*q+1][2]), "+f"(d[1][2*q+1][3])
                         : "r"(a4), "r"(a5), "r"(a6), "r"(a7), "r"(b2), "r"(b3));
        }
    }
}

__device__ __forceinline__ void t4_store(float (&d)[2][4][4], __half* t4s,
                                         int mt0, int cbase, int lane) {
    const int q0 = lane >> 2;
    const int tq = lane & 3;
    #pragma unroll
    for (int mi = 0; mi < 2; mi++) {
        const int rbase = (mt0 + mi) * 16;
        #pragma unroll
        for (int i = 0; i < 4; i++) {
            const int c0 = (cbase + i) * 8 + tq * 2;
            *(__half2*)(t4s + (rbase + q0) * T4_STRIDE + c0) =
                __floats2half2_rn(d[mi][i][0], d[mi][i][1]);
            *(__half2*)(t4s + (rbase + q0 + 8) * T4_STRIDE + c0) =
                __floats2half2_rn(d[mi][i][2], d[mi][i][3]);
        }
    }
}

// Incremental epilogue: i = tid + 896*it over 25088 elements (28 iters exact).
// 896 = 4*196 + 112; 112 = 8*14 -> cl += 4, p += 8, b invariant.
__device__ __forceinline__ void epilogue(const __half* t4s, const float2* w1v,
                                         float* om, int tid, int w1off) {
    int cl = tid / 196;
    int rr = tid - cl * 196;
    int p  = rr / 14;
    int b  = rr - p * 14;
    #pragma unroll 4
    for (int i = tid; i < 25088; i += NT) {
        int l1 = (p == 0) ? 13 : p - 1;
        int l2 = (p < 2) ? p + 12 : p - 2;
        float2 wv = w1v[w1off + cl];
        float v = wv.x * __half2float(t4s[(l1 * 16 + 1 + b) * T4_STRIDE + cl])
                + wv.y * __half2float(t4s[(l2 * 16 + 1 + b) * T4_STRIDE + cl]);
        om[i] = v;
        cl += 4; p += 8;
        if (p >= 14) { p -= 14; cl += 1; }
    }
}

// Bs half (128 c-rows x 384 halves = 48 uint4/row) -> smem, uint4 copies.
// 896 = 18*48 + 32; 7 iterations cover 6144 uint4 (guard on last).
__device__ __forceinline__ void bs_load(char* smem_base, const uint4* src, int tid) {
    int c = tid / 48;
    int w = tid - c * 48;
    #pragma unroll
    for (int it = 0; it < 7; it++) {
        if (c < 128) *(uint4*)(smem_base + c * 784 + w * 16) = src[c * 48 + w];
        c += 18; w += 32;
        if (w >= 48) { w -= 48; c += 1; }
    }
}

__global__ __launch_bounds__(NT, 1) void kMain(const float* __restrict__ x,
                                               const float* __restrict__ w1,
                                               float* __restrict__ out) {
    extern __shared__ char smem[];
    __half* xs  = (__half*)(smem + XS_OFF);
    char*   bsb = smem + BS_OFF;
    __half* t4s = (__half*)(smem + T4_OFF);

    const int tid  = threadIdx.x;
    const int m    = blockIdx.x;
    const int wid  = tid >> 5;
    const int lane = tid & 31;

    // ===== Phase A: build xs via STS.128 (pads zeroed in-loop) + Bs0 =======
    {
        const float* xm = x + (size_t)m * 25088;
        int u  = tid % 226;          // row
        int jb = tid / 226;          // 16B block (8 halves) within row
        #pragma unroll
        for (int it = 0; it < 5; it++) {            // covers 226*16 = 3616 slots
            if (jb < 16) {
                uint4 v = make_uint4(0u, 0u, 0u, 0u);
                const int q = u & 15;
                if (q >= 2 && u < 224) {
                    const float* src = xm + ((u >> 4) * 14 + q - 2);
                    float f0 = src[(jb * 8 + 0) * 196];
                    float f1 = src[(jb * 8 + 1) * 196];
                    float f2 = src[(jb * 8 + 2) * 196];
                    float f3 = src[(jb * 8 + 3) * 196];
                    float f4 = src[(jb * 8 + 4) * 196];
                    float f5 = src[(jb * 8 + 5) * 196];
                    float f6 = src[(jb * 8 + 6) * 196];
                    float f7 = src[(jb * 8 + 7) * 196];
                    __half2 h0 = __floats2half2_rn(f0, f1);
                    __half2 h1 = __floats2half2_rn(f2, f3);
                    __half2 h2 = __floats2half2_rn(f4, f5);
                    __half2 h3 = __floats2half2_rn(f6, f7);
                    v.x = *(uint32_t*)&h0; v.y = *(uint32_t*)&h1;
                    v.z = *(uint32_t*)&h2; v.w = *(uint32_t*)&h3;
                }
                *(uint4*)((char*)xs + u * (XS_STRIDE * 2) + jb * 16) = v;
            }
            u += 218; jb += 3;                      // +896 = 3*226 + 218
            if (u >= 226) { u -= 226; jb += 1; }
        }
    }
    bs_load(bsb, (const uint4*)g_Bh, tid);          // hc=0

    // ---- per-warp constants: 28 warps = 7 m-pairs x 4 n32-groups ----
    const int  mpair  = wid % 7;
    const int  ngrp   = wid / 7;                   // 0..3
    const int  mt0    = mpair * 2;
    const int  cbase  = ngrp * 4;                  // first n8-tile

    GemmCtx g;
    g.a_pre0 = smem_u32(xs) +
        (uint32_t)(((mt0 * 16 + (lane & 15)) * XS_STRIDE + ((lane >> 4) << 3)) * 2);
    g.a_pre1 = g.a_pre0 + (uint32_t)(16 * XS_STRIDE * 2);
    {
        const int n_in16 = (((lane >> 4) & 1) << 3) + (lane & 7);
        const int k_half = ((lane >> 3) & 1) << 3;
        g.b_pre = smem_u32(bsb) +
            (uint32_t)(((cbase * 8 + n_in16) * BS_STRIDE + k_half) * 2);
    }

    float* om = out + (size_t)m * 50176;
    const float2* w1v = (const float2*)w1;

    float d[2][4][4];
    __syncthreads();

    // ===== gemm(0) + t4s store(0) folded (t4s disjoint from xs/Bs reads) ===
    gemm_phase(d, g);
    t4_store(d, t4s, mt0, cbase, lane);
    __syncthreads();   // t4s0 complete; Bs0 reads complete

    // ===== Bs(1) load (own short phase) =====================================
    bs_load(bsb, (const uint4*)(g_Bh + 128 * 384), tid);    // hc=1
    __syncthreads();

    // ===== epilogue(0) then gemm(1); disjoint read sets, no barrier ========
    epilogue(t4s, w1v, om, tid, 0);
    gemm_phase(d, g);
    __syncthreads();   // epi0 t4s reads complete before t4s1 overwrite

    // ===== t4s store(1) =====================================================
    t4_store(d, t4s, mt0, cbase, lane);
    __syncthreads();

    // ===== epilogue(1) ======================================================
    epilogue(t4s, w1v, om + 25088, tid, 128);
}

// ===========================================================================
extern "C" void kernel_launch(void* const* d_in, const int* in_sizes, int n_in,
                              void* d_out, int out_size) {
    const float* x  = (const float*)d_in[0];   // (1024, 1792, 14)
    const float* w1 = (const float*)d_in[1];   // (256, 2)
    const float* w2 = (const float*)d_in[2];   // (128, 3, 256)
    float* out = (float*)d_out;                // (1024, 256, 14, 14)

    static int attr_done = 0;
    if (!attr_done) {
        cudaFuncSetAttribute(kMain, cudaFuncAttributeMaxDynamicSharedMemorySize,
                             SMEM_BYTES);
        attr_done = 1;
    }

    kB<<<384, 256>>>(w2);
    kMain<<<1024, NT, SMEM_BYTES>>>(x, w1, out);
}